// round 15
// baseline (speedup 1.0000x reference)
#include <cuda_runtime.h>
#include <cuda_bf16.h>
#include <stdint.h>

// Problem constants (fixed by reference: B=16, NT=4096, D=512, V=2545)
#define B_  16
#define NT_ 4096
#define D_  512
#define V_  2545
#define D_VEC (D_ / 4)               // 128 float4 per embedding row
#define NROWS (B_ * NT_)             // 65536 output rows
#define NPREP 128                    // prep blocks (8 chunks x 16 batches)
#define CHUNK (NT_ / 8)              // 512 positions per prep chunk

#define NTILES (NROWS / 8)           // 8192 copy tiles (8 rows each)
#define GRIDSZ 1184                  // 148 SMs x 8 resident blocks = ONE wave

// Scratch (device allocations forbidden -> __device__ global)
__device__ int g_tok[NROWS];   // source token per output row (+1 applied), or -1 => zeros

// ---------------------------------------------------------------------------
// Prep kernel (proven R7 config): 128 blocks x 512 threads.
//  (a) dtype probe (int64 little-endian word-pairs vs int32);
//  (b) valid-token count L_b;
//  (c) stretch mapping for this block's 512 positions -> g_tok.
// ---------------------------------------------------------------------------
__global__ void __launch_bounds__(512)
prep_kernel(const int* __restrict__ t32) {
    const int b     = blockIdx.x >> 3;
    const int chunk = blockIdx.x & 7;
    const int tid   = threadIdx.x;

    int bad = 0;
    if (tid < 256) {
        const int lo = t32[2 * tid];
        const int hi = t32[2 * tid + 1];
        const int want_hi = (lo < 0) ? -1 : 0;
        if (hi != want_hi || lo < -1 || lo >= V_) bad = 1;
    }
    const int is64 = __syncthreads_or(bad) ? 0 : 1;
    const int stride = is64 ? 2 : 1;
    const int* row = t32 + (size_t)b * NT_ * stride;

    int cnt = 0;
    #pragma unroll
    for (int i = tid; i < NT_; i += 512)
        cnt += (row[(size_t)i * stride] >= 0);
    #pragma unroll
    for (int off = 16; off > 0; off >>= 1)
        cnt += __shfl_down_sync(0xFFFFFFFFu, cnt, off);

    __shared__ int s_part[16];
    if ((tid & 31) == 0) s_part[tid >> 5] = cnt;
    __syncthreads();
    __shared__ int s_L;
    if (tid == 0) {
        int total = 0;
        for (int w = 0; w < 16; ++w) total += s_part[w];
        s_L = total;
    }
    __syncthreads();
    const int L = s_L;

    const int p = chunk * CHUNK + tid;
    int* tok_row = g_tok + b * NT_;
    if (L <= 0) {
        tok_row[p] = -1;
    } else {
        const unsigned base = (unsigned)NT_ / (unsigned)L;
        const unsigned rem  = (unsigned)NT_ % (unsigned)L;
        const unsigned boundary = ((unsigned)L - rem) * base;
        unsigned j;
        if ((unsigned)p < boundary) j = (unsigned)p / base;
        else                        j = ((unsigned)L - rem) + ((unsigned)p - boundary) / (base + 1);
        int t = row[(size_t)j * stride] + 1;    // [1, V] for valid prefix
        tok_row[p] = min(max(t, 0), V_);        // hard safety clamp
    }
}

// ---------------------------------------------------------------------------
// Persistent single-wave copy kernel: 1184 blocks x 256 threads, all
// resident at once (__launch_bounds__(256, 8) caps regs at 32). Each block
// loops over ~7 tiles (tile = bid + t*GRIDSZ keeps stores spread across L2
// slices). Body = proven R3/R7 gather-copy: MLP=4 LDG.128 + 4 streaming
// STG.128. Eliminates 6 wave transitions + setup/teardown of ~7000 blocks;
// successive loop iterations pipeline (stores of tile i overlap loads of
// tile i+1).
// ---------------------------------------------------------------------------
__global__ void __launch_bounds__(256, 8)
persistent_copy_kernel(const float4* __restrict__ emb,
                       float4* __restrict__ out) {
    const int lane = threadIdx.x & 127;
    const int sub  = threadIdx.x >> 7;          // 0 or 1

    for (int tile = blockIdx.x; tile < NTILES; tile += GRIDSZ) {
        const int rowBase = tile * 8 + sub;

        int tok[4];
        #pragma unroll
        for (int k = 0; k < 4; ++k)
            tok[k] = __ldg(&g_tok[rowBase + 2 * k]);

        float4 v[4];
        #pragma unroll
        for (int k = 0; k < 4; ++k) {
            if (tok[k] >= 0)
                v[k] = __ldg(emb + (size_t)tok[k] * D_VEC + lane);
            else
                v[k] = make_float4(0.f, 0.f, 0.f, 0.f);
        }

        #pragma unroll
        for (int k = 0; k < 4; ++k)
            __stcs(out + (size_t)(rowBase + 2 * k) * D_VEC + lane, v[k]);
    }
}

// ---------------------------------------------------------------------------
// Launch. Identify inputs by element count:
//   text: 65536 elements (int32 or int64) or 131072 int32-words; the
//         device-side probe resolves the layout.
//   emb : (2545+1)*512 = 1303552 fp32.
// ---------------------------------------------------------------------------
extern "C" void kernel_launch(void* const* d_in, const int* in_sizes, int n_in,
                              void* d_out, int out_size) {
    const int*   text = nullptr;
    const float* emb  = nullptr;
    for (int i = 0; i < n_in; ++i) {
        if (in_sizes[i] == NROWS || in_sizes[i] == 2 * NROWS)
            text = (const int*)d_in[i];
        else if (in_sizes[i] == (V_ + 1) * D_)
            emb = (const float*)d_in[i];
    }

    prep_kernel<<<NPREP, 512>>>(text);
    persistent_copy_kernel<<<GRIDSZ, 256>>>((const float4*)emb, (float4*)d_out);
    (void)out_size;
}